// round 1
// baseline (speedup 1.0000x reference)
#include <cuda_runtime.h>

#define B_DIM 8
#define T_DIM 4000
#define D_DIM 1024
#define G_DIM 5
#define L_DIM (T_DIM / G_DIM)      // 800
#define NTOK (B_DIM * T_DIM)       // 32000
#define NGRP (B_DIM * G_DIM)       // 40
#define EPS 1e-5f

// Scratch (no allocations allowed)
__device__ float g_tok_sum[NTOK];
__device__ float g_tok_sumsq[NTOK];
__device__ float g_grp_mean[NGRP];
__device__ float g_grp_rstd[NGRP];

// ---------------------------------------------------------------------------
// Kernel 1: per-token sum / sumsq.  One 256-thread block per token (D=1024,
// float4 => 1 float4 per thread).
// ---------------------------------------------------------------------------
__global__ void tok_stats_kernel(const float* __restrict__ x) {
    const int tok = blockIdx.x;
    const int tid = threadIdx.x;
    const float4 v = reinterpret_cast<const float4*>(x)[(size_t)tok * (D_DIM / 4) + tid];

    float s  = v.x + v.y + v.z + v.w;
    float ss = v.x * v.x + v.y * v.y + v.z * v.z + v.w * v.w;

    // warp reduce
    #pragma unroll
    for (int o = 16; o > 0; o >>= 1) {
        s  += __shfl_down_sync(0xffffffffu, s,  o);
        ss += __shfl_down_sync(0xffffffffu, ss, o);
    }

    __shared__ float sh_s[8];
    __shared__ float sh_ss[8];
    const int warp = tid >> 5, lane = tid & 31;
    if (lane == 0) { sh_s[warp] = s; sh_ss[warp] = ss; }
    __syncthreads();

    if (warp == 0) {
        float a  = (lane < 8) ? sh_s[lane]  : 0.0f;
        float b2 = (lane < 8) ? sh_ss[lane] : 0.0f;
        #pragma unroll
        for (int o = 4; o > 0; o >>= 1) {
            a  += __shfl_down_sync(0xffffffffu, a,  o);
            b2 += __shfl_down_sync(0xffffffffu, b2, o);
        }
        if (lane == 0) {
            g_tok_sum[tok]   = a;
            g_tok_sumsq[tok] = b2;
        }
    }
}

// ---------------------------------------------------------------------------
// Kernel 2: group stats.  One block per (b, g), reduce L=800 token partials.
// ---------------------------------------------------------------------------
__global__ void grp_stats_kernel() {
    const int bg = blockIdx.x;              // 0..39
    const int b  = bg / G_DIM;
    const int g  = bg - b * G_DIM;
    const int tok0 = b * T_DIM + g * L_DIM;
    const int tid = threadIdx.x;

    float s = 0.0f, ss = 0.0f;
    for (int i = tid; i < L_DIM; i += blockDim.x) {
        s  += g_tok_sum[tok0 + i];
        ss += g_tok_sumsq[tok0 + i];
    }

    #pragma unroll
    for (int o = 16; o > 0; o >>= 1) {
        s  += __shfl_down_sync(0xffffffffu, s,  o);
        ss += __shfl_down_sync(0xffffffffu, ss, o);
    }

    __shared__ float sh_s[8];
    __shared__ float sh_ss[8];
    const int warp = tid >> 5, lane = tid & 31;
    if (lane == 0) { sh_s[warp] = s; sh_ss[warp] = ss; }
    __syncthreads();

    if (tid == 0) {
        float ts = 0.0f, tss = 0.0f;
        #pragma unroll
        for (int w = 0; w < 8; ++w) { ts += sh_s[w]; tss += sh_ss[w]; }
        const float inv_n = 1.0f / (float)(L_DIM * D_DIM);
        const float m = ts * inv_n;
        const float v = tss * inv_n - m * m;
        g_grp_mean[bg] = m;
        g_grp_rstd[bg] = rsqrtf(v + EPS);
    }
}

// ---------------------------------------------------------------------------
// Kernel 3: apply.  One block per token.  Fold the 0.5*GN + 0.5*LN blend into
// a single per-token affine  y = x*A + C, then y*w + b.
// ---------------------------------------------------------------------------
__global__ void apply_kernel(const float* __restrict__ x,
                             const float* __restrict__ weight,
                             const float* __restrict__ bias,
                             float* __restrict__ out) {
    const int tok = blockIdx.x;
    const int tid = threadIdx.x;

    const int b  = tok / T_DIM;
    const int t  = tok - b * T_DIM;
    const int bg = b * G_DIM + t / L_DIM;

    const float inv_d = 1.0f / (float)D_DIM;
    const float ts  = g_tok_sum[tok];
    const float tss = g_tok_sumsq[tok];
    const float tm  = ts * inv_d;
    const float tv  = tss * inv_d - tm * tm;
    const float tr  = rsqrtf(tv + EPS);

    const float gm = g_grp_mean[bg];
    const float gr = g_grp_rstd[bg];

    // 0.5*gr*(x-gm) + 0.5*tr*(x-tm) = x*A + C
    const float A = 0.5f * (gr + tr);
    const float C = -0.5f * (gm * gr + tm * tr);

    const float4 xv = reinterpret_cast<const float4*>(x)[(size_t)tok * (D_DIM / 4) + tid];
    const float4 wv = reinterpret_cast<const float4*>(weight)[tid];
    const float4 bv = reinterpret_cast<const float4*>(bias)[tid];

    float4 o;
    o.x = (xv.x * A + C) * wv.x + bv.x;
    o.y = (xv.y * A + C) * wv.y + bv.y;
    o.z = (xv.z * A + C) * wv.z + bv.z;
    o.w = (xv.w * A + C) * wv.w + bv.w;

    reinterpret_cast<float4*>(out)[(size_t)tok * (D_DIM / 4) + tid] = o;
}

// ---------------------------------------------------------------------------
extern "C" void kernel_launch(void* const* d_in, const int* in_sizes, int n_in,
                              void* d_out, int out_size) {
    const float* x      = (const float*)d_in[0];
    // d_in[1] = mask (dense ones; only G is needed, which is fixed at 5)
    const float* weight = (const float*)d_in[2];
    const float* bias   = (const float*)d_in[3];
    float* out          = (float*)d_out;

    tok_stats_kernel<<<NTOK, 256>>>(x);
    grp_stats_kernel<<<NGRP, 256>>>();
    apply_kernel<<<NTOK, 256>>>(x, weight, bias, out);
}

// round 2
// speedup vs baseline: 1.1224x; 1.1224x over previous
#include <cuda_runtime.h>

#define B_DIM 8
#define T_DIM 4000
#define D_DIM 1024
#define G_DIM 5
#define L_DIM (T_DIM / G_DIM)      // 800
#define NTOK (B_DIM * T_DIM)      // 32000
#define NGRP (B_DIM * G_DIM)      // 40
#define EPS 1e-5f
#define TPB 4                     // tokens per block
#define NV4 (D_DIM / 4)           // 256 float4 per token

// Scratch (no allocations allowed)
__device__ float g_tok_sum[NTOK];
__device__ float g_tok_sumsq[NTOK];
__device__ float g_grp_mean[NGRP];
__device__ float g_grp_rstd[NGRP];

// ---------------------------------------------------------------------------
// Kernel 1: per-token sum / sumsq.
// 4 tokens per 256-thread block; 64 threads per token; 4 float4 loads each
// (MLP=4 per thread to hide DRAM latency).
// ---------------------------------------------------------------------------
__global__ void tok_stats_kernel(const float4* __restrict__ x) {
    const int tid    = threadIdx.x;
    const int sub    = tid >> 6;          // token within block (0..3)
    const int lane64 = tid & 63;
    const int tok    = blockIdx.x * TPB + sub;
    const size_t base = (size_t)tok * NV4 + lane64;

    const float4 v0 = x[base];
    const float4 v1 = x[base + 64];
    const float4 v2 = x[base + 128];
    const float4 v3 = x[base + 192];

    float s  = (v0.x + v0.y) + (v0.z + v0.w)
             + (v1.x + v1.y) + (v1.z + v1.w)
             + (v2.x + v2.y) + (v2.z + v2.w)
             + (v3.x + v3.y) + (v3.z + v3.w);
    float ss = v0.x*v0.x + v0.y*v0.y + v0.z*v0.z + v0.w*v0.w
             + v1.x*v1.x + v1.y*v1.y + v1.z*v1.z + v1.w*v1.w
             + v2.x*v2.x + v2.y*v2.y + v2.z*v2.z + v2.w*v2.w
             + v3.x*v3.x + v3.y*v3.y + v3.z*v3.z + v3.w*v3.w;

    // warp reduce (32 lanes)
    #pragma unroll
    for (int o = 16; o > 0; o >>= 1) {
        s  += __shfl_down_sync(0xffffffffu, s,  o);
        ss += __shfl_down_sync(0xffffffffu, ss, o);
    }

    __shared__ float sh_s[8];
    __shared__ float sh_ss[8];
    const int warp = tid >> 5, lane = tid & 31;
    if (lane == 0) { sh_s[warp] = s; sh_ss[warp] = ss; }
    __syncthreads();

    // warps 2j, 2j+1 belong to token j
    if (tid < TPB) {
        const int t = blockIdx.x * TPB + tid;
        g_tok_sum[t]   = sh_s[2 * tid]  + sh_s[2 * tid + 1];
        g_tok_sumsq[t] = sh_ss[2 * tid] + sh_ss[2 * tid + 1];
    }
}

// ---------------------------------------------------------------------------
// Kernel 2: group stats.  One block per (b, g), reduce L=800 token partials.
// ---------------------------------------------------------------------------
__global__ void grp_stats_kernel() {
    const int bg = blockIdx.x;              // 0..39
    const int b  = bg / G_DIM;
    const int g  = bg - b * G_DIM;
    const int tok0 = b * T_DIM + g * L_DIM;
    const int tid = threadIdx.x;

    float s = 0.0f, ss = 0.0f;
    for (int i = tid; i < L_DIM; i += blockDim.x) {
        s  += g_tok_sum[tok0 + i];
        ss += g_tok_sumsq[tok0 + i];
    }

    #pragma unroll
    for (int o = 16; o > 0; o >>= 1) {
        s  += __shfl_down_sync(0xffffffffu, s,  o);
        ss += __shfl_down_sync(0xffffffffu, ss, o);
    }

    __shared__ float sh_s[8];
    __shared__ float sh_ss[8];
    const int warp = tid >> 5, lane = tid & 31;
    if (lane == 0) { sh_s[warp] = s; sh_ss[warp] = ss; }
    __syncthreads();

    if (tid == 0) {
        float ts = 0.0f, tss = 0.0f;
        #pragma unroll
        for (int w = 0; w < 8; ++w) { ts += sh_s[w]; tss += sh_ss[w]; }
        const float inv_n = 1.0f / (float)(L_DIM * D_DIM);
        const float m = ts * inv_n;
        const float v = tss * inv_n - m * m;
        g_grp_mean[bg] = m;
        g_grp_rstd[bg] = rsqrtf(v + EPS);
    }
}

// ---------------------------------------------------------------------------
// Kernel 3: apply.  4 tokens per 256-thread block, 4 float4 x-loads per
// thread.  Fold 0.5*GN + 0.5*LN into one per-token affine y = x*A + C,
// then y*w + b.
// ---------------------------------------------------------------------------
__global__ void apply_kernel(const float4* __restrict__ x,
                             const float4* __restrict__ weight,
                             const float4* __restrict__ bias,
                             float4* __restrict__ out) {
    const int tid    = threadIdx.x;
    const int sub    = tid >> 6;
    const int lane64 = tid & 63;
    const int tok    = blockIdx.x * TPB + sub;

    const int b  = tok / T_DIM;
    const int t  = tok - b * T_DIM;
    const int bg = b * G_DIM + t / L_DIM;

    const float inv_d = 1.0f / (float)D_DIM;
    const float ts  = g_tok_sum[tok];     // broadcast across 64 threads
    const float tss = g_tok_sumsq[tok];
    const float tm  = ts * inv_d;
    const float tv  = tss * inv_d - tm * tm;
    const float tr  = rsqrtf(tv + EPS);

    const float gm = g_grp_mean[bg];
    const float gr = g_grp_rstd[bg];

    const float A = 0.5f * (gr + tr);
    const float C = -0.5f * (gm * gr + tm * tr);

    const size_t base = (size_t)tok * NV4 + lane64;

    // issue all x loads first (MLP=4)
    const float4 x0 = x[base];
    const float4 x1 = x[base + 64];
    const float4 x2 = x[base + 128];
    const float4 x3 = x[base + 192];

    const float4 w0 = weight[lane64];
    const float4 w1 = weight[lane64 + 64];
    const float4 w2 = weight[lane64 + 128];
    const float4 w3 = weight[lane64 + 192];

    const float4 b0 = bias[lane64];
    const float4 b1 = bias[lane64 + 64];
    const float4 b2 = bias[lane64 + 128];
    const float4 b3 = bias[lane64 + 192];

    float4 o0, o1, o2, o3;
    o0.x = fmaf(fmaf(x0.x, A, C), w0.x, b0.x);
    o0.y = fmaf(fmaf(x0.y, A, C), w0.y, b0.y);
    o0.z = fmaf(fmaf(x0.z, A, C), w0.z, b0.z);
    o0.w = fmaf(fmaf(x0.w, A, C), w0.w, b0.w);
    o1.x = fmaf(fmaf(x1.x, A, C), w1.x, b1.x);
    o1.y = fmaf(fmaf(x1.y, A, C), w1.y, b1.y);
    o1.z = fmaf(fmaf(x1.z, A, C), w1.z, b1.z);
    o1.w = fmaf(fmaf(x1.w, A, C), w1.w, b1.w);
    o2.x = fmaf(fmaf(x2.x, A, C), w2.x, b2.x);
    o2.y = fmaf(fmaf(x2.y, A, C), w2.y, b2.y);
    o2.z = fmaf(fmaf(x2.z, A, C), w2.z, b2.z);
    o2.w = fmaf(fmaf(x2.w, A, C), w2.w, b2.w);
    o3.x = fmaf(fmaf(x3.x, A, C), w3.x, b3.x);
    o3.y = fmaf(fmaf(x3.y, A, C), w3.y, b3.y);
    o3.z = fmaf(fmaf(x3.z, A, C), w3.z, b3.z);
    o3.w = fmaf(fmaf(x3.w, A, C), w3.w, b3.w);

    out[base]       = o0;
    out[base + 64]  = o1;
    out[base + 128] = o2;
    out[base + 192] = o3;
}

// ---------------------------------------------------------------------------
extern "C" void kernel_launch(void* const* d_in, const int* in_sizes, int n_in,
                              void* d_out, int out_size) {
    const float4* x      = (const float4*)d_in[0];
    // d_in[1] = mask (dense ones; only G is needed, which is fixed at 5)
    const float4* weight = (const float4*)d_in[2];
    const float4* bias   = (const float4*)d_in[3];
    float4* out          = (float4*)d_out;

    tok_stats_kernel<<<NTOK / TPB, 256>>>(x);
    grp_stats_kernel<<<NGRP, 256>>>();
    apply_kernel<<<NTOK / TPB, 256>>>(x, weight, bias, out);
}

// round 3
// speedup vs baseline: 1.2880x; 1.1475x over previous
#include <cuda_runtime.h>

#define B_DIM 8
#define T_DIM 4000
#define D_DIM 1024
#define G_DIM 5
#define L_DIM (T_DIM / G_DIM)      // 800
#define NTOK (B_DIM * T_DIM)      // 32000
#define NGRP (B_DIM * G_DIM)      // 40
#define EPS 1e-5f
#define NV4 (D_DIM / 4)           // 256 float4 per token
#define WPB 8                     // warps (= tokens) per block

// Scratch (no allocations allowed)
__device__ float g_tok_sum[NTOK];
__device__ float g_tok_sumsq[NTOK];
__device__ float g_grp_mean[NGRP];
__device__ float g_grp_rstd[NGRP];

// ---------------------------------------------------------------------------
// Kernel 1: per-token sum / sumsq.  One WARP per token: 32 lanes x 8 float4
// (MLP=8 per thread).  Warp-shuffle reduce only — no smem, no syncthreads.
// ---------------------------------------------------------------------------
__global__ void tok_stats_kernel(const float4* __restrict__ x) {
    const int tid  = threadIdx.x;
    const int warp = tid >> 5;
    const int lane = tid & 31;
    const int tok  = blockIdx.x * WPB + warp;
    const size_t base = (size_t)tok * NV4 + lane;

    float4 v0 = x[base];
    float4 v1 = x[base + 32];
    float4 v2 = x[base + 64];
    float4 v3 = x[base + 96];
    float4 v4 = x[base + 128];
    float4 v5 = x[base + 160];
    float4 v6 = x[base + 192];
    float4 v7 = x[base + 224];

    float s  = (v0.x + v0.y) + (v0.z + v0.w) + (v1.x + v1.y) + (v1.z + v1.w)
             + (v2.x + v2.y) + (v2.z + v2.w) + (v3.x + v3.y) + (v3.z + v3.w)
             + (v4.x + v4.y) + (v4.z + v4.w) + (v5.x + v5.y) + (v5.z + v5.w)
             + (v6.x + v6.y) + (v6.z + v6.w) + (v7.x + v7.y) + (v7.z + v7.w);
    float ss = v0.x*v0.x + v0.y*v0.y + v0.z*v0.z + v0.w*v0.w
             + v1.x*v1.x + v1.y*v1.y + v1.z*v1.z + v1.w*v1.w
             + v2.x*v2.x + v2.y*v2.y + v2.z*v2.z + v2.w*v2.w
             + v3.x*v3.x + v3.y*v3.y + v3.z*v3.z + v3.w*v3.w
             + v4.x*v4.x + v4.y*v4.y + v4.z*v4.z + v4.w*v4.w
             + v5.x*v5.x + v5.y*v5.y + v5.z*v5.z + v5.w*v5.w
             + v6.x*v6.x + v6.y*v6.y + v6.z*v6.z + v6.w*v6.w
             + v7.x*v7.x + v7.y*v7.y + v7.z*v7.z + v7.w*v7.w;

    #pragma unroll
    for (int o = 16; o > 0; o >>= 1) {
        s  += __shfl_down_sync(0xffffffffu, s,  o);
        ss += __shfl_down_sync(0xffffffffu, ss, o);
    }

    if (lane == 0) {
        g_tok_sum[tok]   = s;
        g_tok_sumsq[tok] = ss;
    }
}

// ---------------------------------------------------------------------------
// Kernel 2: group stats.  One block per (b, g), reduce L=800 token partials.
// ---------------------------------------------------------------------------
__global__ void grp_stats_kernel() {
    const int bg = blockIdx.x;              // 0..39
    const int b  = bg / G_DIM;
    const int g  = bg - b * G_DIM;
    const int tok0 = b * T_DIM + g * L_DIM;
    const int tid = threadIdx.x;

    float s = 0.0f, ss = 0.0f;
    for (int i = tid; i < L_DIM; i += blockDim.x) {
        s  += g_tok_sum[tok0 + i];
        ss += g_tok_sumsq[tok0 + i];
    }

    #pragma unroll
    for (int o = 16; o > 0; o >>= 1) {
        s  += __shfl_down_sync(0xffffffffu, s,  o);
        ss += __shfl_down_sync(0xffffffffu, ss, o);
    }

    __shared__ float sh_s[8];
    __shared__ float sh_ss[8];
    const int warp = tid >> 5, lane = tid & 31;
    if (lane == 0) { sh_s[warp] = s; sh_ss[warp] = ss; }
    __syncthreads();

    if (tid == 0) {
        float ts = 0.0f, tss = 0.0f;
        #pragma unroll
        for (int w = 0; w < 8; ++w) { ts += sh_s[w]; tss += sh_ss[w]; }
        const float inv_n = 1.0f / (float)(L_DIM * D_DIM);
        const float m = ts * inv_n;
        const float v = tss * inv_n - m * m;
        g_grp_mean[bg] = m;
        g_grp_rstd[bg] = rsqrtf(v + EPS);
    }
}

// ---------------------------------------------------------------------------
// Kernel 3: apply.  One WARP per token, 8 float4 x-loads per thread (MLP=8).
// Token order is REVERSED vs tok_stats so the first waves hit the tail of x
// still resident in L2.  Streaming stores keep out from evicting x.
// ---------------------------------------------------------------------------
__global__ void apply_kernel(const float4* __restrict__ x,
                             const float4* __restrict__ weight,
                             const float4* __restrict__ bias,
                             float4* __restrict__ out) {
    const int tid  = threadIdx.x;
    const int warp = tid >> 5;
    const int lane = tid & 31;
    const int tok  = NTOK - 1 - (blockIdx.x * WPB + warp);   // descending

    const int b  = tok / T_DIM;
    const int t  = tok - b * T_DIM;
    const int bg = b * G_DIM + t / L_DIM;

    const float inv_d = 1.0f / (float)D_DIM;
    const float ts  = g_tok_sum[tok];
    const float tss = g_tok_sumsq[tok];
    const float tm  = ts * inv_d;
    const float tv  = tss * inv_d - tm * tm;
    const float tr  = rsqrtf(tv + EPS);

    const float gm = g_grp_mean[bg];
    const float gr = g_grp_rstd[bg];

    const float A = 0.5f * (gr + tr);
    const float C = -0.5f * (gm * gr + tm * tr);

    const size_t base = (size_t)tok * NV4 + lane;

    // all x loads issued first (MLP=8)
    const float4 x0 = x[base];
    const float4 x1 = x[base + 32];
    const float4 x2 = x[base + 64];
    const float4 x3 = x[base + 96];
    const float4 x4 = x[base + 128];
    const float4 x5 = x[base + 160];
    const float4 x6 = x[base + 192];
    const float4 x7 = x[base + 224];

    float4 xs[8] = {x0, x1, x2, x3, x4, x5, x6, x7};

    #pragma unroll
    for (int k = 0; k < 8; ++k) {
        const float4 w = weight[lane + 32 * k];   // L1/L2 resident (4KB total)
        const float4 bb = bias[lane + 32 * k];
        float4 o;
        o.x = fmaf(fmaf(xs[k].x, A, C), w.x, bb.x);
        o.y = fmaf(fmaf(xs[k].y, A, C), w.y, bb.y);
        o.z = fmaf(fmaf(xs[k].z, A, C), w.z, bb.z);
        o.w = fmaf(fmaf(xs[k].w, A, C), w.w, bb.w);
        __stcs(&out[base + 32 * k], o);           // streaming: evict-first
    }
}

// ---------------------------------------------------------------------------
extern "C" void kernel_launch(void* const* d_in, const int* in_sizes, int n_in,
                              void* d_out, int out_size) {
    const float4* x      = (const float4*)d_in[0];
    // d_in[1] = mask (dense ones; only G matters and it is fixed at 5)
    const float4* weight = (const float4*)d_in[2];
    const float4* bias   = (const float4*)d_in[3];
    float4* out          = (float4*)d_out;

    tok_stats_kernel<<<NTOK / WPB, 32 * WPB>>>(x);
    grp_stats_kernel<<<NGRP, 256>>>();
    apply_kernel<<<NTOK / WPB, 32 * WPB>>>(x, weight, bias, out);
}